// round 5
// baseline (speedup 1.0000x reference)
#include <cuda_runtime.h>

// ---------------- problem constants ----------------
#define HN   50
#define DN   8
#define BN   2048
#define TN   512
#define EN   16          // batch elems per CTA
#define NCTA (BN/EN)     // 128
#define NTHR 416         // 13 warps
#define WROW 100         // ull per weight k-row: [j][{if,go}] pairs, 50*2

typedef unsigned long long ull;

// ---- SMEM layout (ull indices) ----
#define H0_OFF   0        // [2][50][16] double-buffered h0, elem-dup packed
#define H1_OFF   1600     // [2][50][16]
#define X2_OFF   3200     // [2][8][16]
#define W0_OFF   3456     // Whh0 [50][100]
#define W1I_OFF  8456     // Wih1 [50][100]
#define W1H_OFF  13456    // Whh1 [50][100]
#define WX_OFF   18456    // Wih0 [8][100]
#define BB_OFF   19256    // biases: 4 x [56]
#define WL_OFF   19480    // head weights (floats, 51 used)
#define TOT_ULL  19512
#define SMEM_BYTES (TOT_ULL*8)   // 156096

// ---------------- f32x2 helpers ----------------
__device__ __forceinline__ ull pack2(float a, float b) {
    ull r; asm("mov.b64 %0, {%1, %2};" : "=l"(r) : "f"(a), "f"(b)); return r;
}
__device__ __forceinline__ ull dup2(float a) { return pack2(a, a); }
__device__ __forceinline__ void fma2(ull& d, ull a, ull b) {
    asm("fma.rn.f32x2 %0, %1, %2, %0;" : "+l"(d) : "l"(a), "l"(b));
}
__device__ __forceinline__ float2 unpk2(ull v) {
    float2 f; asm("mov.b64 {%0, %1}, %2;" : "=f"(f.x), "=f"(f.y) : "l"(v)); return f;
}
__device__ __forceinline__ float sigf(float v) {
    return __fdividef(1.f, 1.f + __expf(-v));
}
__device__ __forceinline__ float tanhx(float v) {
    return fmaf(2.f, __fdividef(1.f, 1.f + __expf(-2.f * v)), -1.f);
}

__device__ __forceinline__ float act_one(ull aif, ull ago, float& c) {
    const float2 vif = unpk2(aif);
    const float2 vgo = unpk2(ago);
    const float i_ = sigf(vif.x);
    const float f_ = sigf(vif.y);
    const float g_ = tanhx(vgo.x);
    const float o_ = sigf(vgo.y);
    c = fmaf(f_, c, i_ * g_);
    return o_ * tanhx(c);
}

__global__ void __launch_bounds__(NTHR, 1)
lstm_fused_kernel(const float* __restrict__ x,
                  const float* __restrict__ Wih0, const float* __restrict__ Whh0,
                  const float* __restrict__ bih0, const float* __restrict__ bhh0,
                  const float* __restrict__ Wih1, const float* __restrict__ Whh1,
                  const float* __restrict__ bih1, const float* __restrict__ bhh1,
                  const float* __restrict__ Wlin, const float* __restrict__ blin,
                  float* __restrict__ out)
{
    extern __shared__ ull sm[];
    ull* h0  = sm + H0_OFF;
    ull* h1  = sm + H1_OFF;
    ull* x2  = sm + X2_OFF;
    ull* W0  = sm + W0_OFF;
    ull* W1i = sm + W1I_OFF;
    ull* W1h = sm + W1H_OFF;
    ull* Wx  = sm + WX_OFF;
    ull* bb  = sm + BB_OFF;
    float* wl = reinterpret_cast<float*>(sm + WL_OFF);

    const int tid  = threadIdx.x;
    const int cta  = blockIdx.x;
    const int lane = tid & 31;
    const int wid  = tid >> 5;
    const int j    = wid * 4 + (lane & 3);   // hidden unit (valid if < 50)
    const int e2   = (lane >> 2) * 2;        // first of this thread's 2 elems

    // ---- stage weights: [k][j][{if,go}] pair-packed, 16B per j ----
    for (int i = tid; i < HN * HN; i += NTHR) {
        int k = i / HN, jj = i % HN;
        W0 [k * WROW + 2 * jj]     = pack2(Whh0[jj * HN + k],         Whh0[(jj + 50) * HN + k]);
        W0 [k * WROW + 2 * jj + 1] = pack2(Whh0[(jj + 100) * HN + k], Whh0[(jj + 150) * HN + k]);
        W1i[k * WROW + 2 * jj]     = pack2(Wih1[jj * HN + k],         Wih1[(jj + 50) * HN + k]);
        W1i[k * WROW + 2 * jj + 1] = pack2(Wih1[(jj + 100) * HN + k], Wih1[(jj + 150) * HN + k]);
        W1h[k * WROW + 2 * jj]     = pack2(Whh1[jj * HN + k],         Whh1[(jj + 50) * HN + k]);
        W1h[k * WROW + 2 * jj + 1] = pack2(Whh1[(jj + 100) * HN + k], Whh1[(jj + 150) * HN + k]);
    }
    for (int i = tid; i < DN * HN; i += NTHR) {
        int k = i / HN, jj = i % HN;
        Wx[k * WROW + 2 * jj]     = pack2(Wih0[jj * DN + k],          Wih0[(jj + 50) * DN + k]);
        Wx[k * WROW + 2 * jj + 1] = pack2(Wih0[(jj + 100) * DN + k],  Wih0[(jj + 150) * DN + k]);
    }
    for (int i = tid; i < HN; i += NTHR) {
        bb[i]       = pack2(bih0[i]       + bhh0[i],       bih0[i + 50]  + bhh0[i + 50]);
        bb[56 + i]  = pack2(bih0[i + 100] + bhh0[i + 100], bih0[i + 150] + bhh0[i + 150]);
        bb[112 + i] = pack2(bih1[i]       + bhh1[i],       bih1[i + 50]  + bhh1[i + 50]);
        bb[168 + i] = pack2(bih1[i + 100] + bhh1[i + 100], bih1[i + 150] + bhh1[i + 150]);
    }
    if (tid < HN) wl[tid] = Wlin[tid];
    if (tid == HN) wl[HN] = blin[0];
    for (int i = tid; i < 3200; i += NTHR) sm[H0_OFF + i] = 0ULL;  // zero h0,h1 (both buffers)

    // ---- x staging (128 threads: d = tid&7, e = tid>>3) ----
    const int pd = tid & 7, pe = tid >> 3;
    const float* xg = x + ((size_t)(cta * EN + pe) * TN) * DN + pd;
    float xv = 0.f;
    if (tid < 128) {
        x2[pd * 16 + pe] = dup2(xg[0]);      // x[0] into buffer 0
        xv = xg[DN];                          // prefetch x[1]
    }

    __syncthreads();   // staging (incl. bb) visible before register loads

    const ull bif0 = bb[j], bgo0 = bb[56 + j], bif1 = bb[112 + j], bgo1 = bb[168 + j];
    const bool on = (j < HN);
    float c00 = 0.f, c01 = 0.f, c10 = 0.f, c11 = 0.f;

    // Pipelined phases: phase p computes layer0(step p) and layer1(step p-1).
    for (int p = 0; p <= TN; ++p) {
        const int pb = p & 1, qb = pb ^ 1;
        const ull* h0p = h0 + qb * 800 + e2; // h0[p-1]
        const ull* h1p = h1 + pb * 800 + e2; // h1[p-2]
        ull* h0w = h0 + pb * 800;            // h0[p]
        ull* h1w = h1 + qb * 800;            // h1[p-1]

        __syncthreads();

        ull a0if0, a0go0, a0if1, a0go1, a1if0, a1go0, a1if1, a1go1;
        if (on) {
            a0if0 = a0if1 = bif0;  a0go0 = a0go1 = bgo0;
            a1if0 = a1if1 = bif1;  a1go0 = a1go1 = bgo1;

            const ull* w0r  = W0  + 2 * j;
            const ull* w1ir = W1i + 2 * j;
            const ull* w1hr = W1h + 2 * j;

            // merged K=50: h0[p-1] feeds W0 (a0) and W1i (a1); h1[p-2] feeds W1h (a1)
#pragma unroll 5
            for (int k = 0; k < HN; ++k) {
                const ulonglong2 w0  = *reinterpret_cast<const ulonglong2*>(w0r  + k * WROW);
                const ulonglong2 w1i = *reinterpret_cast<const ulonglong2*>(w1ir + k * WROW);
                const ulonglong2 w1h = *reinterpret_cast<const ulonglong2*>(w1hr + k * WROW);
                const ulonglong2 hh0 = *reinterpret_cast<const ulonglong2*>(h0p + k * 16);
                const ulonglong2 hh1 = *reinterpret_cast<const ulonglong2*>(h1p + k * 16);
                fma2(a0if0, w0.x,  hh0.x); fma2(a0go0, w0.y,  hh0.x);
                fma2(a0if1, w0.x,  hh0.y); fma2(a0go1, w0.y,  hh0.y);
                fma2(a1if0, w1i.x, hh0.x); fma2(a1go0, w1i.y, hh0.x);
                fma2(a1if1, w1i.x, hh0.y); fma2(a1go1, w1i.y, hh0.y);
                fma2(a1if0, w1h.x, hh1.x); fma2(a1go0, w1h.y, hh1.x);
                fma2(a1if1, w1h.x, hh1.y); fma2(a1go1, w1h.y, hh1.y);
            }
            // layer0 input: x[p]
            const ull* xp  = x2 + pb * 128 + e2;
            const ull* wxr = Wx + 2 * j;
#pragma unroll
            for (int k = 0; k < DN; ++k) {
                const ulonglong2 wx = *reinterpret_cast<const ulonglong2*>(wxr + k * WROW);
                const ulonglong2 xx = *reinterpret_cast<const ulonglong2*>(xp + k * 16);
                fma2(a0if0, wx.x, xx.x); fma2(a0go0, wx.y, xx.x);
                fma2(a0if1, wx.x, xx.y); fma2(a0go1, wx.y, xx.y);
            }
        }

        // stage x[p+1] into buf (p+1)&1, prefetch x[p+2]
        if (tid < 128) {
            x2[qb * 128 + pd * 16 + pe] = dup2(xv);
            int tn = p + 2; if (tn > TN - 1) tn = TN - 1;
            xv = xg[(size_t)tn * DN];
        }

        if (on && p < TN) {    // layer0(p) -> h0[p]
            float v0 = act_one(a0if0, a0go0, c00);
            float v1 = act_one(a0if1, a0go1, c01);
            ulonglong2 s; s.x = dup2(v0); s.y = dup2(v1);
            *reinterpret_cast<ulonglong2*>(h0w + j * 16 + e2) = s;
        }
        if (on && p > 0) {     // layer1(p-1) -> h1[p-1]
            float v0 = act_one(a1if0, a1go0, c10);
            float v1 = act_one(a1if1, a1go1, c11);
            ulonglong2 s; s.x = dup2(v0); s.y = dup2(v1);
            *reinterpret_cast<ulonglong2*>(h1w + j * 16 + e2) = s;
        }
    }

    __syncthreads();
    // final h1[TN-1] lives in buffer (TN-1)&1 = 1
    if (tid < EN) {
        float acc = wl[HN];
#pragma unroll 10
        for (int jj = 0; jj < HN; ++jj)
            acc = fmaf(*reinterpret_cast<const float*>(h1 + 800 + jj * 16 + tid), wl[jj], acc);
        out[cta * EN + tid] = acc;
    }
}

extern "C" void kernel_launch(void* const* d_in, const int* in_sizes, int n_in,
                              void* d_out, int out_size)
{
    const float* x    = (const float*)d_in[0];
    const float* Wih0 = (const float*)d_in[1];
    const float* Whh0 = (const float*)d_in[2];
    const float* bih0 = (const float*)d_in[3];
    const float* bhh0 = (const float*)d_in[4];
    const float* Wih1 = (const float*)d_in[5];
    const float* Whh1 = (const float*)d_in[6];
    const float* bih1 = (const float*)d_in[7];
    const float* bhh1 = (const float*)d_in[8];
    const float* Wlin = (const float*)d_in[9];
    const float* blin = (const float*)d_in[10];
    float* out = (float*)d_out;

    cudaFuncSetAttribute(lstm_fused_kernel,
                         cudaFuncAttributeMaxDynamicSharedMemorySize, SMEM_BYTES);
    lstm_fused_kernel<<<NCTA, NTHR, SMEM_BYTES>>>(
        x, Wih0, Whh0, bih0, bhh0, Wih1, Whh1, bih1, bhh1, Wlin, blin, out);
}

// round 7
// speedup vs baseline: 2.9516x; 2.9516x over previous
#include <cuda_runtime.h>
#include <cuda_bf16.h>
#include <cstdint>

typedef uint32_t u32;

#define HN 50
#define TN 512
#define EN 16
#define NCTA 128
#define NTHR 416   // 13 warps

#define BROW 272
#define BTILE (16*BROW)                  // 4352
#define SM_B      0                      // [2 buf][hi,lo] B tiles
#define SM_A1LO   (4*BTILE)              // A1 lo-part [208 rows][272B]
#define SM_G0     (SM_A1LO + 208*272)    // gates layer0 [208][20 f32]
#define SM_G1     (SM_G0 + 208*80)
#define SM_BIAS0  (SM_G1 + 208*80)
#define SM_BIAS1  (SM_BIAS0 + 800)
#define SM_WL     (SM_BIAS1 + 800)
#define SMEM_BYTES (SM_WL + 256)         // ~109 KB

__device__ __forceinline__ u32 smem_u32(const void* p){
    u32 a; asm("{ .reg .u64 t; cvta.to.shared.u64 t, %1; cvt.u32.u64 %0, t; }" : "=r"(a) : "l"(p));
    return a;
}
__device__ __forceinline__ u32 pk2bf(__nv_bfloat16 a, __nv_bfloat16 b){
    return (u32)__bfloat16_as_ushort(a) | ((u32)__bfloat16_as_ushort(b) << 16);
}
__device__ __forceinline__ void mma_bf16(float* c, const u32* a, u32 b0, u32 b1){
    asm volatile("mma.sync.aligned.m16n8k16.row.col.f32.bf16.bf16.f32 "
                 "{%0,%1,%2,%3}, {%4,%5,%6,%7}, {%8,%9}, {%0,%1,%2,%3};"
                 : "+f"(c[0]), "+f"(c[1]), "+f"(c[2]), "+f"(c[3])
                 : "r"(a[0]), "r"(a[1]), "r"(a[2]), "r"(a[3]), "r"(b0), "r"(b1));
}
__device__ __forceinline__ void ldsm4(u32* r, u32 addr){
    asm volatile("ldmatrix.sync.aligned.m8n8.x4.shared.b16 {%0,%1,%2,%3}, [%4];"
                 : "=r"(r[0]), "=r"(r[1]), "=r"(r[2]), "=r"(r[3]) : "r"(addr));
}
__device__ __forceinline__ float sigf(float v){
    return __fdividef(1.f, 1.f + __expf(-v));
}
__device__ __forceinline__ float tanhx(float v){
    return fmaf(2.f, __fdividef(1.f, 1.f + __expf(-2.f * v)), -1.f);
}

// A0 [208 x 64]: cols 0-49 Whh0, 50-55 zero, 56-63 Wih0
__device__ __forceinline__ float w0elem(int g, int k, const float* Whh0, const float* Wih0){
    if (g >= 200) return 0.f;
    if (k < 50)  return Whh0[g * 50 + k];
    if (k >= 56) return Wih0[g * 8 + (k - 56)];
    return 0.f;
}
// A1 [208 x 128]: cols 0-49 Wih1, 64-113 Whh1, else zero
__device__ __forceinline__ float w1elem(int g, int k, const float* Wih1, const float* Whh1){
    if (g >= 200) return 0.f;
    if (k < 50)  return Wih1[g * 50 + k];
    if (k >= 64 && k < 114) return Whh1[g * 50 + (k - 64)];
    return 0.f;
}

__global__ void __launch_bounds__(NTHR, 1)
lstm_mma_kernel(const float* __restrict__ x,
                const float* __restrict__ Wih0, const float* __restrict__ Whh0,
                const float* __restrict__ bih0, const float* __restrict__ bhh0,
                const float* __restrict__ Wih1, const float* __restrict__ Whh1,
                const float* __restrict__ bih1, const float* __restrict__ bhh1,
                const float* __restrict__ Wlin, const float* __restrict__ blin,
                float* __restrict__ out)
{
    extern __shared__ char sm[];
    const u32 smb = smem_u32(sm);
    const int tid  = threadIdx.x;
    const int cta  = blockIdx.x;
    const int lane = tid & 31;
    const int wrp  = tid >> 5;          // 0..12, each owns one M=16 tile

    float* bias0 = (float*)(sm + SM_BIAS0);
    float* bias1 = (float*)(sm + SM_BIAS1);
    float* wl    = (float*)(sm + SM_WL);
    float* g0p   = (float*)(sm + SM_G0);
    float* g1p   = (float*)(sm + SM_G1);

    // ---- init: biases, head, zero B (both buffers, hi+lo), A1-lo tile ----
    for (int i = tid; i < 200; i += NTHR){
        bias0[i] = bih0[i] + bhh0[i];
        bias1[i] = bih1[i] + bhh1[i];
    }
    if (tid < HN) wl[tid] = Wlin[tid];
    if (tid == HN) wl[HN] = blin[0];
    for (int i = tid; i < 4 * BTILE / 4; i += NTHR)
        ((u32*)(sm + SM_B))[i] = 0;
    for (int i = tid; i < 208 * 128; i += NTHR){
        const int g = i >> 7, k = i & 127;
        const float v = w1elem(g, k, Wih1, Whh1);
        const float lo = v - __bfloat162float(__float2bfloat16_rn(v));
        *(__nv_bfloat16*)(sm + SM_A1LO + g * 272 + k * 2) = __float2bfloat16_rn(lo);
    }

    // ---- build register A fragments ----
    const int m0  = wrp * 16;
    const int gid = lane >> 2;
    const int c0  = (lane & 3) * 2;
    u32 A0hi[4][4], A0lo[4][4], A1hi[8][4];
#pragma unroll
    for (int kt = 0; kt < 4; ++kt)
#pragma unroll
        for (int q = 0; q < 4; ++q){
            const int g = m0 + gid + ((q & 1) ? 8 : 0);
            const int k = kt * 16 + c0 + ((q & 2) ? 8 : 0);
            const float e0 = w0elem(g, k, Whh0, Wih0);
            const float e1 = w0elem(g, k + 1, Whh0, Wih0);
            const __nv_bfloat16 h0b = __float2bfloat16_rn(e0);
            const __nv_bfloat16 h1b = __float2bfloat16_rn(e1);
            A0hi[kt][q] = pk2bf(h0b, h1b);
            A0lo[kt][q] = pk2bf(__float2bfloat16_rn(e0 - __bfloat162float(h0b)),
                                __float2bfloat16_rn(e1 - __bfloat162float(h1b)));
        }
#pragma unroll
    for (int kt = 0; kt < 8; ++kt)
#pragma unroll
        for (int q = 0; q < 4; ++q){
            const int g = m0 + gid + ((q & 1) ? 8 : 0);
            const int k = kt * 16 + c0 + ((q & 2) ? 8 : 0);
            A1hi[kt][q] = pk2bf(__float2bfloat16_rn(w1elem(g, k, Wih1, Whh1)),
                                __float2bfloat16_rn(w1elem(g, k + 1, Wih1, Whh1)));
        }

    // ---- lane offsets for ldmatrix ----
    const int grp = lane >> 3, ln8 = lane & 7;
    const u32 bOffLane = (u32)((ln8 + ((grp >= 2) ? 8 : 0)) * BROW + ((grp & 1) ? 16 : 0));
    const u32 aOffLane = (u32)((m0 + ln8 + ((grp & 1) ? 8 : 0)) * 272 + ((grp >= 2) ? 16 : 0));
    const u32 a1loLane = smb + SM_A1LO + aOffLane;

    // ---- act roles (threads 0..399) ----
    const bool is_act = (tid < 400);
    const int lay = (tid < 200) ? 0 : 1;
    const int at  = (tid < 200) ? tid : tid - 200;
    const int aj  = at % 50;
    const int ae4 = (at / 50) * 4;

    __syncthreads();   // init staging visible

    float bi = 0.f, bf_ = 0.f, bg = 0.f, bo = 0.f;
    if (is_act){
        const float* bp = lay ? bias1 : bias0;
        bi = bp[aj]; bf_ = bp[aj + 50]; bg = bp[aj + 100]; bo = bp[aj + 150];
    }
    float cc[4] = {0.f, 0.f, 0.f, 0.f};

    // ---- x stagers: threads 400..415 = elem s ----
    const int s = tid - 400;
    const float* xgp = (tid >= 400) ? (x + ((size_t)(cta * EN + s) * TN) * 8) : x;
    float xv[8];
    if (tid >= 400){
#pragma unroll
        for (int d = 0; d < 8; ++d) xv[d] = xgp[d];   // x[0]
        char* bh = sm + SM_B;           // buffer 0 hi
        u32 hw[4], lw[4];
#pragma unroll
        for (int i = 0; i < 4; ++i){
            const float a = xv[2 * i], b = xv[2 * i + 1];
            const __nv_bfloat16 ha = __float2bfloat16_rn(a), hb = __float2bfloat16_rn(b);
            hw[i] = pk2bf(ha, hb);
            lw[i] = pk2bf(__float2bfloat16_rn(a - __bfloat162float(ha)),
                          __float2bfloat16_rn(b - __bfloat162float(hb)));
        }
        *(uint4*)(bh + s * BROW + 112)         = *(uint4*)hw;
        *(uint4*)(bh + BTILE + s * BROW + 112) = *(uint4*)lw;
#pragma unroll
        for (int d = 0; d < 8; ++d) xv[d] = xgp[8 + d];  // prefetch x[1]
    }

    // ================= phase loop: phase p = layer0(p) + layer1(p-1) =================
    for (int p = 0; p <= TN; ++p){
        const int b = p & 1, nb = b ^ 1;

        __syncthreads();   // barrier A: B tile (h, x) for phase p ready

        // ---- MMA (all 13 warps) ----
        {
            float acc0[2][4] = {{0.f,0.f,0.f,0.f},{0.f,0.f,0.f,0.f}};
            float acc1[2][4] = {{0.f,0.f,0.f,0.f},{0.f,0.f,0.f,0.f}};
            const u32 bhiA = smb + SM_B + (u32)(b * 2 * BTILE) + bOffLane;
            const u32 bloA = bhiA + BTILE;
#pragma unroll
            for (int kt = 0; kt < 8; ++kt){
                u32 bh[4], bl[4], wlo[4];
                ldsm4(bh, bhiA + kt * 32);
                ldsm4(bl, bloA + kt * 32);
                ldsm4(wlo, a1loLane + kt * 32);
                if (kt < 4){
                    mma_bf16(acc0[0], A0hi[kt], bh[0], bh[1]); mma_bf16(acc0[1], A0hi[kt], bh[2], bh[3]);
                    mma_bf16(acc0[0], A0lo[kt], bh[0], bh[1]); mma_bf16(acc0[1], A0lo[kt], bh[2], bh[3]);
                    mma_bf16(acc0[0], A0hi[kt], bl[0], bl[1]); mma_bf16(acc0[1], A0hi[kt], bl[2], bl[3]);
                }
                mma_bf16(acc1[0], A1hi[kt], bh[0], bh[1]); mma_bf16(acc1[1], A1hi[kt], bh[2], bh[3]);
                mma_bf16(acc1[0], wlo,      bh[0], bh[1]); mma_bf16(acc1[1], wlo,      bh[2], bh[3]);
                mma_bf16(acc1[0], A1hi[kt], bl[0], bl[1]); mma_bf16(acc1[1], A1hi[kt], bl[2], bl[3]);
            }
            // ---- STS gates ----
            const int r = m0 + gid;
            *(float2*)(g0p + r * 20 + c0)           = make_float2(acc0[0][0], acc0[0][1]);
            *(float2*)(g0p + (r + 8) * 20 + c0)     = make_float2(acc0[0][2], acc0[0][3]);
            *(float2*)(g0p + r * 20 + 8 + c0)       = make_float2(acc0[1][0], acc0[1][1]);
            *(float2*)(g0p + (r + 8) * 20 + 8 + c0) = make_float2(acc0[1][2], acc0[1][3]);
            *(float2*)(g1p + r * 20 + c0)           = make_float2(acc1[0][0], acc1[0][1]);
            *(float2*)(g1p + (r + 8) * 20 + c0)     = make_float2(acc1[0][2], acc1[0][3]);
            *(float2*)(g1p + r * 20 + 8 + c0)       = make_float2(acc1[1][0], acc1[1][1]);
            *(float2*)(g1p + (r + 8) * 20 + 8 + c0) = make_float2(acc1[1][2], acc1[1][3]);
        }

        __syncthreads();   // barrier B: gates visible

        // ---- activations ----
        if (is_act && ((lay == 0) ? (p < TN) : (p > 0))){
            const float* gp = lay ? g1p : g0p;
            const float4 gi = *(const float4*)(gp + aj * 20 + ae4);
            const float4 gf = *(const float4*)(gp + (aj + 50) * 20 + ae4);
            const float4 gg = *(const float4*)(gp + (aj + 100) * 20 + ae4);
            const float4 go = *(const float4*)(gp + (aj + 150) * 20 + ae4);
            float v[4];
            {
                const float i0 = sigf(gi.x + bi), f0 = sigf(gf.x + bf_);
                const float q0 = tanhx(gg.x + bg), o0 = sigf(go.x + bo);
                cc[0] = fmaf(f0, cc[0], i0 * q0); v[0] = o0 * tanhx(cc[0]);
                const float i1 = sigf(gi.y + bi), f1 = sigf(gf.y + bf_);
                const float q1 = tanhx(gg.y + bg), o1 = sigf(go.y + bo);
                cc[1] = fmaf(f1, cc[1], i1 * q1); v[1] = o1 * tanhx(cc[1]);
                const float i2 = sigf(gi.z + bi), f2 = sigf(gf.z + bf_);
                const float q2 = tanhx(gg.z + bg), o2 = sigf(go.z + bo);
                cc[2] = fmaf(f2, cc[2], i2 * q2); v[2] = o2 * tanhx(cc[2]);
                const float i3 = sigf(gi.w + bi), f3 = sigf(gf.w + bf_);
                const float q3 = tanhx(gg.w + bg), o3 = sigf(go.w + bo);
                cc[3] = fmaf(f3, cc[3], i3 * q3); v[3] = o3 * tanhx(cc[3]);
            }
            if (lay == 1 && p == TN){
                // final h1 -> stash f32 into gates0 for the head
                *(float4*)(g0p + aj * 20 + ae4) = make_float4(v[0], v[1], v[2], v[3]);
            } else {
                char* bh = sm + SM_B + nb * 2 * BTILE;
                char* bl = bh + BTILE;
                const int colB = lay ? (64 + aj) : aj;
#pragma unroll
                for (int m = 0; m < 4; ++m){
                    const __nv_bfloat16 hv = __float2bfloat16_rn(v[m]);
                    *(__nv_bfloat16*)(bh + (ae4 + m) * BROW + colB * 2) = hv;
                    *(__nv_bfloat16*)(bl + (ae4 + m) * BROW + colB * 2) =
                        __float2bfloat16_rn(v[m] - __bfloat162float(hv));
                }
            }
        }

        // ---- x staging for phase p+1 ----
        if (tid >= 400 && (p + 1) < TN){
            char* bh = sm + SM_B + nb * 2 * BTILE;
            u32 hw[4], lw[4];
#pragma unroll
            for (int i = 0; i < 4; ++i){
                const float a = xv[2 * i], bq = xv[2 * i + 1];
                const __nv_bfloat16 ha = __float2bfloat16_rn(a), hb = __float2bfloat16_rn(bq);
                hw[i] = pk2bf(ha, hb);
                lw[i] = pk2bf(__float2bfloat16_rn(a - __bfloat162float(ha)),
                              __float2bfloat16_rn(bq - __bfloat162float(hb)));
            }
            *(uint4*)(bh + s * BROW + 112)         = *(uint4*)hw;
            *(uint4*)(bh + BTILE + s * BROW + 112) = *(uint4*)lw;
            int tn = p + 2; if (tn > TN - 1) tn = TN - 1;
#pragma unroll
            for (int d = 0; d < 8; ++d) xv[d] = xgp[(size_t)tn * 8 + d];
        }
    }

    __syncthreads();

    // ---- linear head on stashed h1 ----
    if (tid < EN){
        float acc = wl[HN];
#pragma unroll 10
        for (int j = 0; j < HN; ++j)
            acc = fmaf(g0p[j * 20 + tid], wl[j], acc);
        out[cta * EN + tid] = acc;
    }
}

extern "C" void kernel_launch(void* const* d_in, const int* in_sizes, int n_in,
                              void* d_out, int out_size)
{
    const float* x    = (const float*)d_in[0];
    const float* Wih0 = (const float*)d_in[1];
    const float* Whh0 = (const float*)d_in[2];
    const float* bih0 = (const float*)d_in[3];
    const float* bhh0 = (const float*)d_in[4];
    const float* Wih1 = (const float*)d_in[5];
    const float* Whh1 = (const float*)d_in[6];
    const float* bih1 = (const float*)d_in[7];
    const float* bhh1 = (const float*)d_in[8];
    const float* Wlin = (const float*)d_in[9];
    const float* blin = (const float*)d_in[10];
    float* out = (float*)d_out;

    cudaFuncSetAttribute(lstm_mma_kernel,
                         cudaFuncAttributeMaxDynamicSharedMemorySize, SMEM_BYTES);
    lstm_mma_kernel<<<NCTA, NTHR, SMEM_BYTES>>>(
        x, Wih0, Whh0, bih0, bhh0, Wih1, Whh1, bih1, bhh1, Wlin, blin, out);
}